// round 16
// baseline (speedup 1.0000x reference)
#include <cuda_runtime.h>
#include <cuda_bf16.h>
#include <cstdint>
#include <math.h>

// ---------------- problem constants ----------------
#define TT   256
#define BB   32
#define HH   512
#define GG   2048      // 4*H
#define EE   256
#define H2   1024      // 2*H
#define LL   9
#define MM   (TT*BB)   // 8192
#define NW   (GG * HH) // one w_hh matrix: 2048x512

// ---------------- device scratch ----------------
__device__ float g_x0[MM * EE];
__device__ float g_x1[MM * H2];
__device__ float g_x2[MM * H2];
__device__ float g_pre_f[(size_t)MM * GG];
__device__ float g_pre_r[(size_t)MM * GG];
__device__ unsigned short g_hbh[2][2][HH * BB];  // h hi  [buf][dir][k*32+b]
__device__ unsigned short g_hbm[2][2][HH * BB];  // h mid
__device__ volatile unsigned g_arr[128];
__device__ volatile unsigned g_gen;
// bf16 split buffers (input projections)
__device__ unsigned short g_Ah[MM * H2];
__device__ unsigned short g_Am[MM * H2];
__device__ unsigned short g_Whf[GG * H2];
__device__ unsigned short g_Wmf[GG * H2];
__device__ unsigned short g_Whr[GG * H2];
__device__ unsigned short g_Wmr[GG * H2];
// w_hh bf16 splits (4 matrices: l0f, l0r, l1f, l1r)
__device__ unsigned short g_WHh[4 * NW];
__device__ unsigned short g_WHm[4 * NW];

__device__ __forceinline__ float sigf(float x) { return 1.0f / (1.0f + __expf(-x)); }
__device__ __forceinline__ float tanhfast(float x) {
    float e = __expf(2.0f * x);
    return (e - 1.0f) / (e + 1.0f);
}

__device__ __forceinline__ unsigned smem_u32(const void* p) {
    unsigned a;
    asm("{ .reg .u64 t; cvta.to.shared.u64 t, %1; cvt.u32.u64 %0, t; }"
        : "=r"(a) : "l"(p));
    return a;
}

// ---------------- mma.sync helpers ----------------
__device__ __forceinline__ void ldsm4(unsigned& r0, unsigned& r1, unsigned& r2,
                                      unsigned& r3, unsigned addr) {
    asm volatile("ldmatrix.sync.aligned.m8n8.x4.shared.b16 {%0,%1,%2,%3}, [%4];"
                 : "=r"(r0), "=r"(r1), "=r"(r2), "=r"(r3) : "r"(addr));
}
__device__ __forceinline__ void ldsm4t(unsigned& r0, unsigned& r1, unsigned& r2,
                                       unsigned& r3, unsigned addr) {
    asm volatile("ldmatrix.sync.aligned.m8n8.x4.trans.shared.b16 {%0,%1,%2,%3}, [%4];"
                 : "=r"(r0), "=r"(r1), "=r"(r2), "=r"(r3) : "r"(addr));
}
__device__ __forceinline__ void mma_bf16(float& d0, float& d1, float& d2, float& d3,
                                         unsigned a0, unsigned a1, unsigned a2,
                                         unsigned a3, unsigned b0, unsigned b1) {
    asm volatile(
        "mma.sync.aligned.m16n8k16.row.col.f32.bf16.bf16.f32 "
        "{%0,%1,%2,%3}, {%4,%5,%6,%7}, {%8,%9}, {%0,%1,%2,%3};"
        : "+f"(d0), "+f"(d1), "+f"(d2), "+f"(d3)
        : "r"(a0), "r"(a1), "r"(a2), "r"(a3), "r"(b0), "r"(b1));
}

// ---------------- embedding ----------------
__global__ void embed_k(const int* __restrict__ ids, const float* __restrict__ table,
                        float* __restrict__ x0) {
    int gid = blockIdx.x * blockDim.x + threadIdx.x;
    if (gid >= MM * EE / 4) return;
    int e4 = gid & 63;
    int m  = gid >> 6;
    int t  = m >> 5;
    int b  = m & 31;
    int id = ids[b * TT + t];
    reinterpret_cast<float4*>(x0)[gid] =
        reinterpret_cast<const float4*>(table)[(size_t)id * 64 + e4];
}

// ---------------- fp32 -> (bf16 hi, bf16 mid) split helpers ----------------
__device__ __forceinline__ void split4(float4 x, ushort4& h, ushort4& m) {
    __nv_bfloat16 t;
    t = __float2bfloat16(x.x); h.x = __bfloat16_as_ushort(t);
    m.x = __bfloat16_as_ushort(__float2bfloat16(x.x - __bfloat162float(t)));
    t = __float2bfloat16(x.y); h.y = __bfloat16_as_ushort(t);
    m.y = __bfloat16_as_ushort(__float2bfloat16(x.y - __bfloat162float(t)));
    t = __float2bfloat16(x.z); h.z = __bfloat16_as_ushort(t);
    m.z = __bfloat16_as_ushort(__float2bfloat16(x.z - __bfloat162float(t)));
    t = __float2bfloat16(x.w); h.w = __bfloat16_as_ushort(t);
    m.w = __bfloat16_as_ushort(__float2bfloat16(x.w - __bfloat162float(t)));
}

__global__ void split_bf16(const float* __restrict__ src, unsigned short* __restrict__ hi,
                           unsigned short* __restrict__ mid, int n4) {
    int i = blockIdx.x * blockDim.x + threadIdx.x;
    if (i >= n4) return;
    ushort4 h, m;
    split4(reinterpret_cast<const float4*>(src)[i], h, m);
    reinterpret_cast<ushort4*>(hi)[i]  = h;
    reinterpret_cast<ushort4*>(mid)[i] = m;
}

// fused: all 4 w_hh matrices in one launch (blockIdx.y selects)
__global__ void split4_whh(const float* __restrict__ s0, const float* __restrict__ s1,
                           const float* __restrict__ s2, const float* __restrict__ s3,
                           unsigned short* __restrict__ hi,
                           unsigned short* __restrict__ mid) {
    int i = blockIdx.x * blockDim.x + threadIdx.x;
    if (i >= NW / 4) return;
    int mat = blockIdx.y;
    const float* src = (mat == 0) ? s0 : (mat == 1) ? s1 : (mat == 2) ? s2 : s3;
    ushort4 h, m;
    split4(reinterpret_cast<const float4*>(src)[i], h, m);
    size_t o = (size_t)mat * (NW / 4) + i;
    reinterpret_cast<ushort4*>(hi)[o]  = h;
    reinterpret_cast<ushort4*>(mid)[o] = m;
}

// fused: both dirs' w_ih in one launch (blockIdx.y selects)
__global__ void split2_wih(const float* __restrict__ sf, const float* __restrict__ sr,
                           int n4) {
    int i = blockIdx.x * blockDim.x + threadIdx.x;
    if (i >= n4) return;
    ushort4 h, m;
    if (blockIdx.y == 0) {
        split4(reinterpret_cast<const float4*>(sf)[i], h, m);
        reinterpret_cast<ushort4*>(g_Whf)[i] = h;
        reinterpret_cast<ushort4*>(g_Wmf)[i] = m;
    } else {
        split4(reinterpret_cast<const float4*>(sr)[i], h, m);
        reinterpret_cast<ushort4*>(g_Whr)[i] = h;
        reinterpret_cast<ushort4*>(g_Wmr)[i] = m;
    }
}

// ---------------- mma.sync bf16 split GEMM (R12-exact) ----------
#define RSB 80
#define TLB (128 * RSB)
__global__ __launch_bounds__(256, 2) void gemm_mma(
    const unsigned short* __restrict__ Ah, const unsigned short* __restrict__ Am, int K,
    const float* __restrict__ b1f, const float* __restrict__ b2f,
    const float* __restrict__ b1r, const float* __restrict__ b2r,
    float* __restrict__ Cf, float* __restrict__ Cr) {
    __shared__ unsigned char sraw[4 * TLB];
    __shared__ float sbias[128];

    const unsigned short *Wh, *Wm; const float *b1, *b2; float* C;
    if (blockIdx.z == 0) { Wh = g_Whf; Wm = g_Wmf; b1 = b1f; b2 = b2f; C = Cf; }
    else                 { Wh = g_Whr; Wm = g_Wmr; b1 = b1r; b2 = b2r; C = Cr; }

    int m0 = blockIdx.y * 128, n0 = blockIdx.x * 128;
    int tid = threadIdx.x, warp = tid >> 5, lane = tid & 31;
    int wm = warp >> 2, wn = warp & 3;

    if (tid < 128) sbias[tid] = b1[n0 + tid] + b2[n0 + tid];

    unsigned sbase = smem_u32(sraw);
    int tl = lane >> 3, r8 = lane & 7;
    int mn_off = (tl & 1) * 8 + r8;
    int k_off = (tl >> 1) * 8;

    float d[4][4][4];
#pragma unroll
    for (int i = 0; i < 4; i++)
#pragma unroll
        for (int j = 0; j < 4; j++)
#pragma unroll
            for (int q = 0; q < 4; q++) d[i][j][q] = 0.0f;

    int ldr = tid >> 1, ldh = tid & 1;

    for (int kc0 = 0; kc0 < K; kc0 += 32) {
        {
            size_t ga = (size_t)(m0 + ldr) * K + kc0 + ldh * 16;
            size_t gb = (size_t)(n0 + ldr) * K + kc0 + ldh * 16;
            unsigned so = ldr * RSB + ldh * 32;
            *reinterpret_cast<uint4*>(sraw + 0 * TLB + so) =
                *reinterpret_cast<const uint4*>(Ah + ga);
            *reinterpret_cast<uint4*>(sraw + 0 * TLB + so + 16) =
                *reinterpret_cast<const uint4*>(Ah + ga + 8);
            *reinterpret_cast<uint4*>(sraw + 1 * TLB + so) =
                *reinterpret_cast<const uint4*>(Am + ga);
            *reinterpret_cast<uint4*>(sraw + 1 * TLB + so + 16) =
                *reinterpret_cast<const uint4*>(Am + ga + 8);
            *reinterpret_cast<uint4*>(sraw + 2 * TLB + so) =
                *reinterpret_cast<const uint4*>(Wh + gb);
            *reinterpret_cast<uint4*>(sraw + 2 * TLB + so + 16) =
                *reinterpret_cast<const uint4*>(Wh + gb + 8);
            *reinterpret_cast<uint4*>(sraw + 3 * TLB + so) =
                *reinterpret_cast<const uint4*>(Wm + gb);
            *reinterpret_cast<uint4*>(sraw + 3 * TLB + so + 16) =
                *reinterpret_cast<const uint4*>(Wm + gb + 8);
        }
        __syncthreads();

#pragma unroll
        for (int kh = 0; kh < 2; kh++) {
#pragma unroll
            for (int ps = 0; ps < 3; ps++) {
                unsigned ab = (ps == 2) ? 1u * TLB : 0u * TLB;
                unsigned bb = (ps == 1) ? 3u * TLB : 2u * TLB;
                unsigned a[4][4], bfr[2][4];
#pragma unroll
                for (int i = 0; i < 4; i++) {
                    unsigned ao = sbase + ab +
                        (wm * 64 + i * 16 + mn_off) * RSB + (kh * 16 + k_off) * 2;
                    ldsm4(a[i][0], a[i][1], a[i][2], a[i][3], ao);
                }
#pragma unroll
                for (int j16 = 0; j16 < 2; j16++) {
                    unsigned bo = sbase + bb +
                        (wn * 32 + j16 * 16 + mn_off) * RSB + (kh * 16 + k_off) * 2;
                    ldsm4(bfr[j16][0], bfr[j16][1], bfr[j16][2], bfr[j16][3], bo);
                }
#pragma unroll
                for (int i = 0; i < 4; i++)
#pragma unroll
                    for (int j = 0; j < 4; j++) {
                        int jj = j >> 1, p = j & 1;
                        mma_bf16(d[i][j][0], d[i][j][1], d[i][j][2], d[i][j][3],
                                 a[i][0], a[i][1], a[i][2], a[i][3],
                                 bfr[jj][p], bfr[jj][p + 2]);
                    }
            }
        }
        __syncthreads();
    }

    int r = lane >> 2, c2 = (lane & 3) * 2;
#pragma unroll
    for (int i = 0; i < 4; i++) {
#pragma unroll
        for (int j = 0; j < 4; j++) {
            int colL = wn * 32 + j * 8 + c2;
            int col = n0 + colL;
            int row0 = m0 + wm * 64 + i * 16 + r;
            float2 o0, o1;
            o0.x = d[i][j][0] + sbias[colL];
            o0.y = d[i][j][1] + sbias[colL + 1];
            o1.x = d[i][j][2] + sbias[colL];
            o1.y = d[i][j][3] + sbias[colL + 1];
            *reinterpret_cast<float2*>(C + (size_t)row0 * GG + col) = o0;
            *reinterpret_cast<float2*>(C + (size_t)(row0 + 8) * GG + col) = o1;
        }
    }
}

// ---------------- persistent bidirectional LSTM recurrence (v7) ----------------
// v6 (HMMA dot) + merged reduce/activation: activation threads (tid<256) sum
// their 4 gate rows x 16 chunks directly from sP, eliminating the sG stage and
// one __syncthreads. Barrier machinery = R12-exact.
#define RSH 80
#define RSW 1040
#define SWH_OFF 0u
#define SWM_OFF 33280u
#define SHH_OFF 66560u
#define SHM_OFF 107520u
#define SP_OFF  148480u
#define REC_SMEM 222336
__global__ __launch_bounds__(512) void lstm_rec(
    const float* __restrict__ pre_f, const float* __restrict__ pre_r,
    const unsigned short* __restrict__ Whf_hi, const unsigned short* __restrict__ Whf_mi,
    const unsigned short* __restrict__ Whr_hi, const unsigned short* __restrict__ Whr_mi,
    float* __restrict__ xout) {
    extern __shared__ unsigned char smc[];
    float* sP = reinterpret_cast<float*>(smc + SP_OFF);
    unsigned sbase = smem_u32(smc);

    int blk = blockIdx.x;
    int dir = blk >> 6;
    int j0 = (blk & 63) * 8;
    const float* pre = dir ? pre_r : pre_f;
    const unsigned short* Whi = dir ? Whr_hi : Whf_hi;
    const unsigned short* Wmi = dir ? Whr_mi : Whf_mi;

    int tid = threadIdx.x;
    int warp = tid >> 5, lane = tid & 31;
    int ua = tid >> 5, ba = tid & 31;            // activation (tid<256)
    int tl = lane >> 3, r8 = lane & 7;
    int mn_off = (tl & 1) * 8 + r8;              // B frags (n rows)
    int k_off = (tl >> 1) * 8;                   // B frags (k)
    int kA = (tl >> 1) * 8 + r8;                 // A trans frags: stored k row
    int bA = (tl & 1) * 8;                       // A trans frags: b col

    unsigned gen0 = g_gen;

    // ---- load W slice (32 rows x 512 k, hi+mid) into smem ----
    for (int i = tid; i < 2048; i += 512) {
        int row = i >> 6, c16 = i & 63;
        int g = row >> 3, u = row & 7;
        size_t src = (size_t)(g * HH + j0 + u) * 64 + c16;
        *reinterpret_cast<uint4*>(smc + SWH_OFF + row * RSW + c16 * 16) =
            reinterpret_cast<const uint4*>(Whi)[src];
        *reinterpret_cast<uint4*>(smc + SWM_OFF + row * RSW + c16 * 16) =
            reinterpret_cast<const uint4*>(Wmi)[src];
    }

    if (tid < 256) {
        g_hbh[0][dir][(j0 + ua) * BB + ba] = 0;
        g_hbm[0][dir][(j0 + ua) * BB + ba] = 0;
    }
    float creg = 0.0f;

    // ---- initial full-grid barrier (R12-exact) ----
    __threadfence();
    __syncthreads();
    if (blk == 0) {
        if (tid >= 1 && tid < 128) {
            unsigned tg = gen0 + 1u;
            while ((int)(g_arr[tid] - tg) < 0) { }
            __threadfence();
        }
        __syncthreads();
        if (tid == 0) { __threadfence(); g_gen = gen0 + 1u; }
    } else {
        if (tid == 0) {
            g_arr[blk] = gen0 + 1u;
            unsigned tg = gen0 + 1u;
            while ((int)(g_gen - tg) < 0) { }
            __threadfence();
        }
        __syncthreads();
    }

    unsigned hb = SHH_OFF + warp * 2560;
    unsigned mb = SHM_OFF + warp * 2560;
    int wk = warp * 32;

    for (int s = 0; s < TT; s++) {
        int t = dir ? (TT - 1 - s) : s;
        int cur = s & 1, nxt = cur ^ 1;

        // ---- stage this warp's 32-k chunk of split h ----
        {
            const uint4* gh = reinterpret_cast<const uint4*>(&g_hbh[cur][dir][0]) + warp * 128;
            const uint4* gm = reinterpret_cast<const uint4*>(&g_hbm[cur][dir][0]) + warp * 128;
#pragma unroll
            for (int q = 0; q < 4; q++) {
                int i = lane + 32 * q;
                unsigned so = (i >> 2) * RSH + (i & 3) * 16;
                *reinterpret_cast<uint4*>(smc + hb + so) = gh[i];
                *reinterpret_cast<uint4*>(smc + mb + so) = gm[i];
            }
        }

        // pre for activation (tid<256): 4 gate rows, this (unit, batch)
        float p4[4];
        if (tid < 256) {
            const float* pre_t = pre + (size_t)t * (BB * GG) + (size_t)ba * GG + j0 + ua;
#pragma unroll
            for (int g = 0; g < 4; g++) p4[g] = pre_t[g * HH];
        }

        __syncwarp();

        // ---- HMMA dot: D[32b x 32n] partial over this warp's 32 k ----
        float d[2][4][4];
#pragma unroll
        for (int i = 0; i < 2; i++)
#pragma unroll
            for (int j = 0; j < 4; j++)
#pragma unroll
                for (int q = 0; q < 4; q++) d[i][j][q] = 0.0f;

#pragma unroll
        for (int ps = 0; ps < 3; ps++) {
            unsigned Abase = sbase + ((ps == 2) ? mb : hb);
            unsigned Bbase = sbase + ((ps == 1) ? SWM_OFF : SWH_OFF);
#pragma unroll
            for (int ks = 0; ks < 2; ks++) {
                int kb = ks * 16;
                unsigned a[2][4], bfr[2][4];
#pragma unroll
                for (int mt = 0; mt < 2; mt++) {
                    unsigned ao = Abase + (kb + kA) * RSH + (mt * 16 + bA) * 2;
                    ldsm4t(a[mt][0], a[mt][1], a[mt][2], a[mt][3], ao);
                }
#pragma unroll
                for (int j16 = 0; j16 < 2; j16++) {
                    unsigned bo = Bbase + (j16 * 16 + mn_off) * RSW +
                                  (wk + kb + k_off) * 2;
                    ldsm4(bfr[j16][0], bfr[j16][1], bfr[j16][2], bfr[j16][3], bo);
                }
#pragma unroll
                for (int mt = 0; mt < 2; mt++)
#pragma unroll
                    for (int j = 0; j < 4; j++) {
                        int jj = j >> 1, p = j & 1;
                        mma_bf16(d[mt][j][0], d[mt][j][1], d[mt][j][2], d[mt][j][3],
                                 a[mt][0], a[mt][1], a[mt][2], a[mt][3],
                                 bfr[jj][p], bfr[jj][p + 2]);
                    }
            }
        }

        // ---- write partials: sP[warp][nrow][batch] ----
        {
            int r = lane >> 2, c2 = (lane & 3) * 2;
#pragma unroll
            for (int mt = 0; mt < 2; mt++)
#pragma unroll
                for (int j = 0; j < 4; j++) {
                    int nr = j * 8 + c2;
                    int bb_ = mt * 16 + r;
                    sP[((warp * 32) + nr) * 34 + bb_]         = d[mt][j][0];
                    sP[((warp * 32) + nr + 1) * 34 + bb_]     = d[mt][j][1];
                    sP[((warp * 32) + nr) * 34 + bb_ + 8]     = d[mt][j][2];
                    sP[((warp * 32) + nr + 1) * 34 + bb_ + 8] = d[mt][j][3];
                }
        }
        __syncthreads();

        // ---- merged reduce + activation + split-h store ----
        float h = 0.0f;
        if (tid < 256) {
            float gs[4];
#pragma unroll
            for (int g = 0; g < 4; g++) {
                float ss = p4[g];
                int row = g * 8 + ua;
#pragma unroll
                for (int c = 0; c < 16; c++)
                    ss += sP[((c * 32) + row) * 34 + ba];
                gs[g] = ss;
            }
            creg = sigf(gs[1]) * creg + sigf(gs[0]) * tanhfast(gs[2]);
            h = sigf(gs[3]) * tanhfast(creg);
            __nv_bfloat16 hh = __float2bfloat16(h);
            int ha = (j0 + ua) * BB + ba;
            g_hbh[nxt][dir][ha] = __bfloat16_as_ushort(hh);
            g_hbm[nxt][dir][ha] =
                __bfloat16_as_ushort(__float2bfloat16(h - __bfloat162float(hh)));
            __threadfence();
        }
        __syncthreads();

        // ---- full-grid barrier with xout overlap (R12-exact) ----
        unsigned tg = gen0 + (unsigned)s + 2u;
        if (blk == 0) {
            if (tid < 256)
                xout[((size_t)t * BB + ba) * H2 + dir * HH + j0 + ua] = h;
            if (tid >= 1 && tid < 128) {
                while ((int)(g_arr[tid] - tg) < 0) { }
                __threadfence();
            }
            __syncthreads();
            if (tid == 0) { __threadfence(); g_gen = tg; }
        } else {
            if (tid == 0) g_arr[blk] = tg;
            if (tid < 256)
                xout[((size_t)t * BB + ba) * H2 + dir * HH + j0 + ua] = h;
            if (tid == 0) {
                while ((int)(g_gen - tg) < 0) { }
                __threadfence();
            }
            __syncthreads();
        }
    }
}

// ---------------- classifier ----------------
__global__ void cls_k(const float* __restrict__ x2, const float* __restrict__ w,
                      const float* __restrict__ bias, float* __restrict__ out) {
    int gw = (blockIdx.x * blockDim.x + threadIdx.x) >> 5;
    int lane = threadIdx.x & 31;
    if (gw >= MM) return;
    const float* xr = x2 + (size_t)gw * H2;
    float acc[LL];
#pragma unroll
    for (int l = 0; l < LL; l++) acc[l] = 0.0f;
    for (int k = lane; k < H2; k += 32) {
        float xv = xr[k];
#pragma unroll
        for (int l = 0; l < LL; l++) acc[l] = fmaf(xv, w[l * H2 + k], acc[l]);
    }
#pragma unroll
    for (int l = 0; l < LL; l++) {
#pragma unroll
        for (int off = 16; off > 0; off >>= 1)
            acc[l] += __shfl_xor_sync(0xffffffffu, acc[l], off);
    }
    if (lane == 0) {
        int t = gw >> 5, b = gw & 31;
        float* o = out + 1 + ((size_t)b * TT + t) * LL;
#pragma unroll
        for (int l = 0; l < LL; l++) o[l] = acc[l] + bias[l];
    }
}

// ---------------- CRF NLL ----------------
__global__ void crf_k(const float* __restrict__ dout, const int* __restrict__ labels,
                      const int* __restrict__ mask, const float* __restrict__ start,
                      const float* __restrict__ endv, const float* __restrict__ trans,
                      float* __restrict__ out) {
    __shared__ float alpha[BB][LL];
    __shared__ float sc[BB];
    __shared__ float lz[BB];
    __shared__ int   prev[BB];
    __shared__ float tr[LL][LL];
    int tid = threadIdx.x;
    int b = tid / LL, l = tid % LL;
    if (tid < LL * LL) tr[tid / LL][tid % LL] = trans[tid];
    __syncthreads();
    const float* em = dout + 1;

    alpha[b][l] = start[l] + em[((size_t)b * TT) * LL + l];
    if (l == 0) {
        int tg = labels[b * TT]; if (tg < 0) tg = 0;
        sc[b] = start[tg] + em[((size_t)b * TT) * LL + tg];
        prev[b] = tg;
    }
    __syncthreads();

    for (int t = 1; t < TT; t++) {
        int on = mask[b * TT + t];
        float m = -1e30f;
#pragma unroll
        for (int p = 0; p < LL; p++) m = fmaxf(m, alpha[b][p] + tr[p][l]);
        float s = 0.0f;
#pragma unroll
        for (int p = 0; p < LL; p++) s += __expf(alpha[b][p] + tr[p][l] - m);
        float nxt = m + __logf(s) + em[((size_t)b * TT + t) * LL + l];
        __syncthreads();
        if (on) alpha[b][l] = nxt;
        if (l == 0) {
            int tg = labels[b * TT + t]; if (tg < 0) tg = 0;
            float mk = (float)mask[b * TT + t];
            sc[b] += (tr[prev[b]][tg] + em[((size_t)b * TT + t) * LL + tg]) * mk;
            if (on) prev[b] = tg;
        }
        __syncthreads();
    }
    if (l == 0) {
        sc[b] += endv[prev[b]];
        float m = -1e30f;
#pragma unroll
        for (int p = 0; p < LL; p++) m = fmaxf(m, alpha[b][p] + endv[p]);
        float s = 0.0f;
#pragma unroll
        for (int p = 0; p < LL; p++) s += __expf(alpha[b][p] + endv[p] - m);
        lz[b] = m + __logf(s);
    }
    __syncthreads();
    if (tid == 0) {
        float loss = 0.0f;
        for (int bb = 0; bb < BB; bb++) loss += sc[bb] - lz[bb];
        out[0] = -loss / (float)BB;
    }
}

// ---------------- host launch ----------------
extern "C" void kernel_launch(void* const* d_in, const int* in_sizes, int n_in,
                              void* d_out, int out_size) {
    const int*   ids    = (const int*)d_in[0];
    const int*   amask  = (const int*)d_in[1];
    const int*   labels = (const int*)d_in[2];
    const float* emb    = (const float*)d_in[3];
    const float* w_ih_l0_f = (const float*)d_in[4];
    const float* w_hh_l0_f = (const float*)d_in[5];
    const float* b_ih_l0_f = (const float*)d_in[6];
    const float* b_hh_l0_f = (const float*)d_in[7];
    const float* w_ih_l0_r = (const float*)d_in[8];
    const float* w_hh_l0_r = (const float*)d_in[9];
    const float* b_ih_l0_r = (const float*)d_in[10];
    const float* b_hh_l0_r = (const float*)d_in[11];
    const float* w_ih_l1_f = (const float*)d_in[12];
    const float* w_hh_l1_f = (const float*)d_in[13];
    const float* b_ih_l1_f = (const float*)d_in[14];
    const float* b_hh_l1_f = (const float*)d_in[15];
    const float* w_ih_l1_r = (const float*)d_in[16];
    const float* w_hh_l1_r = (const float*)d_in[17];
    const float* b_ih_l1_r = (const float*)d_in[18];
    const float* b_hh_l1_r = (const float*)d_in[19];
    const float* cls_w  = (const float*)d_in[20];
    const float* cls_b  = (const float*)d_in[21];
    const float* crf_s  = (const float*)d_in[22];
    const float* crf_e  = (const float*)d_in[23];
    const float* crf_t  = (const float*)d_in[24];
    float* out = (float*)d_out;

    float *x0, *x1, *x2, *pref, *prer;
    unsigned short *ah, *am, *whh_h, *whh_m;
    cudaGetSymbolAddress((void**)&x0,    g_x0);
    cudaGetSymbolAddress((void**)&x1,    g_x1);
    cudaGetSymbolAddress((void**)&x2,    g_x2);
    cudaGetSymbolAddress((void**)&pref,  g_pre_f);
    cudaGetSymbolAddress((void**)&prer,  g_pre_r);
    cudaGetSymbolAddress((void**)&ah,    g_Ah);
    cudaGetSymbolAddress((void**)&am,    g_Am);
    cudaGetSymbolAddress((void**)&whh_h, g_WHh);
    cudaGetSymbolAddress((void**)&whh_m, g_WHm);

    cudaFuncSetAttribute(lstm_rec, cudaFuncAttributeMaxDynamicSharedMemorySize, REC_SMEM);

    // Launch order arranged so lstm_rec(l0) is the 6th launch (ncu -s 5 -c 1).
    embed_k<<<(MM * EE / 4 + 255) / 256, 256>>>(ids, emb, x0);                        // 1
    {
        dim3 g4((NW / 4 + 255) / 256, 4);
        split4_whh<<<g4, 256>>>(w_hh_l0_f, w_hh_l0_r, w_hh_l1_f, w_hh_l1_r,
                                whh_h, whh_m);                                        // 2
    }
    split_bf16<<<(MM * EE / 4 + 255) / 256, 256>>>(x0, ah, am, MM * EE / 4);          // 3
    {
        dim3 g2((GG * EE / 4 + 255) / 256, 2);
        split2_wih<<<g2, 256>>>(w_ih_l0_f, w_ih_l0_r, GG * EE / 4);                   // 4
    }
    {
        dim3 gg(GG / 128, MM / 128, 2);
        gemm_mma<<<gg, 256>>>(ah, am, EE,
                              b_ih_l0_f, b_hh_l0_f, b_ih_l0_r, b_hh_l0_r,
                              pref, prer);                                            // 5
    }
    lstm_rec<<<128, 512, REC_SMEM>>>(pref, prer,
                                     whh_h + 0 * NW, whh_m + 0 * NW,
                                     whh_h + 1 * NW, whh_m + 1 * NW, x1);             // 6

    split_bf16<<<(MM * H2 / 4 + 255) / 256, 256>>>(x1, ah, am, MM * H2 / 4);          // 7
    {
        dim3 g2((GG * H2 / 4 + 255) / 256, 2);
        split2_wih<<<g2, 256>>>(w_ih_l1_f, w_ih_l1_r, GG * H2 / 4);                   // 8
    }
    {
        dim3 gg(GG / 128, MM / 128, 2);
        gemm_mma<<<gg, 256>>>(ah, am, H2,
                              b_ih_l1_f, b_hh_l1_f, b_ih_l1_r, b_hh_l1_r,
                              pref, prer);                                            // 9
    }
    lstm_rec<<<128, 512, REC_SMEM>>>(pref, prer,
                                     whh_h + 2 * NW, whh_m + 2 * NW,
                                     whh_h + 3 * NW, whh_m + 3 * NW, x2);             // 10

    cls_k<<<(MM * 32 + 255) / 256, 256>>>(x2, cls_w, cls_b, out);                     // 11
    crf_k<<<1, BB * LL>>>(out, labels, amask, crf_s, crf_e, crf_t, out);              // 12
}

// round 17
// speedup vs baseline: 1.0640x; 1.0640x over previous
#include <cuda_runtime.h>
#include <cuda_bf16.h>
#include <cstdint>
#include <math.h>

// ---------------- problem constants ----------------
#define TT   256
#define BB   32
#define HH   512
#define GG   2048      // 4*H
#define EE   256
#define H2   1024      // 2*H
#define LL   9
#define MM   (TT*BB)   // 8192
#define NW   (GG * HH) // one w_hh matrix: 2048x512

// ---------------- device scratch ----------------
__device__ float g_x1[MM * H2];
__device__ float g_x2[MM * H2];
__device__ float g_pre_f[(size_t)MM * GG];
__device__ float g_pre_r[(size_t)MM * GG];
__device__ unsigned short g_hbh[2][2][HH * BB];  // h hi  [buf][dir][k*32+b]
__device__ unsigned short g_hbm[2][2][HH * BB];  // h mid
__device__ volatile unsigned g_arr[128];
__device__ volatile unsigned g_gen;
// bf16 split buffers (input projections)
__device__ unsigned short g_Ah[MM * H2];
__device__ unsigned short g_Am[MM * H2];
__device__ unsigned short g_Whf[GG * H2];
__device__ unsigned short g_Wmf[GG * H2];
__device__ unsigned short g_Whr[GG * H2];
__device__ unsigned short g_Wmr[GG * H2];
// w_hh bf16 splits (4 matrices: l0f, l0r, l1f, l1r)
__device__ unsigned short g_WHh[4 * NW];
__device__ unsigned short g_WHm[4 * NW];

__device__ __forceinline__ float sigf(float x) { return 1.0f / (1.0f + __expf(-x)); }
__device__ __forceinline__ float tanhfast(float x) {
    float e = __expf(2.0f * x);
    return (e - 1.0f) / (e + 1.0f);
}

__device__ __forceinline__ unsigned smem_u32(const void* p) {
    unsigned a;
    asm("{ .reg .u64 t; cvta.to.shared.u64 t, %1; cvt.u32.u64 %0, t; }"
        : "=r"(a) : "l"(p));
    return a;
}

// ---------------- mma.sync helpers ----------------
__device__ __forceinline__ void ldsm4(unsigned& r0, unsigned& r1, unsigned& r2,
                                      unsigned& r3, unsigned addr) {
    asm volatile("ldmatrix.sync.aligned.m8n8.x4.shared.b16 {%0,%1,%2,%3}, [%4];"
                 : "=r"(r0), "=r"(r1), "=r"(r2), "=r"(r3) : "r"(addr));
}
__device__ __forceinline__ void ldsm4t(unsigned& r0, unsigned& r1, unsigned& r2,
                                       unsigned& r3, unsigned addr) {
    asm volatile("ldmatrix.sync.aligned.m8n8.x4.trans.shared.b16 {%0,%1,%2,%3}, [%4];"
                 : "=r"(r0), "=r"(r1), "=r"(r2), "=r"(r3) : "r"(addr));
}
__device__ __forceinline__ void mma_bf16(float& d0, float& d1, float& d2, float& d3,
                                         unsigned a0, unsigned a1, unsigned a2,
                                         unsigned a3, unsigned b0, unsigned b1) {
    asm volatile(
        "mma.sync.aligned.m16n8k16.row.col.f32.bf16.bf16.f32 "
        "{%0,%1,%2,%3}, {%4,%5,%6,%7}, {%8,%9}, {%0,%1,%2,%3};"
        : "+f"(d0), "+f"(d1), "+f"(d2), "+f"(d3)
        : "r"(a0), "r"(a1), "r"(a2), "r"(a3), "r"(b0), "r"(b1));
}

// ---------------- fp32 -> (bf16 hi, bf16 mid) split helpers ----------------
__device__ __forceinline__ void split4(float4 x, ushort4& h, ushort4& m) {
    __nv_bfloat16 t;
    t = __float2bfloat16(x.x); h.x = __bfloat16_as_ushort(t);
    m.x = __bfloat16_as_ushort(__float2bfloat16(x.x - __bfloat162float(t)));
    t = __float2bfloat16(x.y); h.y = __bfloat16_as_ushort(t);
    m.y = __bfloat16_as_ushort(__float2bfloat16(x.y - __bfloat162float(t)));
    t = __float2bfloat16(x.z); h.z = __bfloat16_as_ushort(t);
    m.z = __bfloat16_as_ushort(__float2bfloat16(x.z - __bfloat162float(t)));
    t = __float2bfloat16(x.w); h.w = __bfloat16_as_ushort(t);
    m.w = __bfloat16_as_ushort(__float2bfloat16(x.w - __bfloat162float(t)));
}

// embedding fused with bf16 split: x0 never materialized in fp32
__global__ void embed_split(const int* __restrict__ ids, const float* __restrict__ table,
                            unsigned short* __restrict__ hi,
                            unsigned short* __restrict__ mid) {
    int gid = blockIdx.x * blockDim.x + threadIdx.x;
    if (gid >= MM * EE / 4) return;
    int e4 = gid & 63;
    int m  = gid >> 6;
    int t  = m >> 5;
    int b  = m & 31;
    int id = ids[b * TT + t];
    float4 x = reinterpret_cast<const float4*>(table)[(size_t)id * 64 + e4];
    ushort4 h, mm_;
    split4(x, h, mm_);
    reinterpret_cast<ushort4*>(hi)[gid]  = h;
    reinterpret_cast<ushort4*>(mid)[gid] = mm_;
}

__global__ void split_bf16(const float* __restrict__ src, unsigned short* __restrict__ hi,
                           unsigned short* __restrict__ mid, int n4) {
    int i = blockIdx.x * blockDim.x + threadIdx.x;
    if (i >= n4) return;
    ushort4 h, m;
    split4(reinterpret_cast<const float4*>(src)[i], h, m);
    reinterpret_cast<ushort4*>(hi)[i]  = h;
    reinterpret_cast<ushort4*>(mid)[i] = m;
}

// fused: all 4 w_hh matrices in one launch (blockIdx.y selects)
__global__ void split4_whh(const float* __restrict__ s0, const float* __restrict__ s1,
                           const float* __restrict__ s2, const float* __restrict__ s3,
                           unsigned short* __restrict__ hi,
                           unsigned short* __restrict__ mid) {
    int i = blockIdx.x * blockDim.x + threadIdx.x;
    if (i >= NW / 4) return;
    int mat = blockIdx.y;
    const float* src = (mat == 0) ? s0 : (mat == 1) ? s1 : (mat == 2) ? s2 : s3;
    ushort4 h, m;
    split4(reinterpret_cast<const float4*>(src)[i], h, m);
    size_t o = (size_t)mat * (NW / 4) + i;
    reinterpret_cast<ushort4*>(hi)[o]  = h;
    reinterpret_cast<ushort4*>(mid)[o] = m;
}

// fused: both dirs' w_ih in one launch (blockIdx.y selects)
__global__ void split2_wih(const float* __restrict__ sf, const float* __restrict__ sr,
                           int n4) {
    int i = blockIdx.x * blockDim.x + threadIdx.x;
    if (i >= n4) return;
    ushort4 h, m;
    if (blockIdx.y == 0) {
        split4(reinterpret_cast<const float4*>(sf)[i], h, m);
        reinterpret_cast<ushort4*>(g_Whf)[i] = h;
        reinterpret_cast<ushort4*>(g_Wmf)[i] = m;
    } else {
        split4(reinterpret_cast<const float4*>(sr)[i], h, m);
        reinterpret_cast<ushort4*>(g_Whr)[i] = h;
        reinterpret_cast<ushort4*>(g_Wmr)[i] = m;
    }
}

// ---------------- mma.sync bf16 split GEMM (R12-exact) ----------
#define RSB 80
#define TLB (128 * RSB)
__global__ __launch_bounds__(256, 2) void gemm_mma(
    const unsigned short* __restrict__ Ah, const unsigned short* __restrict__ Am, int K,
    const float* __restrict__ b1f, const float* __restrict__ b2f,
    const float* __restrict__ b1r, const float* __restrict__ b2r,
    float* __restrict__ Cf, float* __restrict__ Cr) {
    __shared__ unsigned char sraw[4 * TLB];
    __shared__ float sbias[128];

    const unsigned short *Wh, *Wm; const float *b1, *b2; float* C;
    if (blockIdx.z == 0) { Wh = g_Whf; Wm = g_Wmf; b1 = b1f; b2 = b2f; C = Cf; }
    else                 { Wh = g_Whr; Wm = g_Wmr; b1 = b1r; b2 = b2r; C = Cr; }

    int m0 = blockIdx.y * 128, n0 = blockIdx.x * 128;
    int tid = threadIdx.x, warp = tid >> 5, lane = tid & 31;
    int wm = warp >> 2, wn = warp & 3;

    if (tid < 128) sbias[tid] = b1[n0 + tid] + b2[n0 + tid];

    unsigned sbase = smem_u32(sraw);
    int tl = lane >> 3, r8 = lane & 7;
    int mn_off = (tl & 1) * 8 + r8;
    int k_off = (tl >> 1) * 8;

    float d[4][4][4];
#pragma unroll
    for (int i = 0; i < 4; i++)
#pragma unroll
        for (int j = 0; j < 4; j++)
#pragma unroll
            for (int q = 0; q < 4; q++) d[i][j][q] = 0.0f;

    int ldr = tid >> 1, ldh = tid & 1;

    for (int kc0 = 0; kc0 < K; kc0 += 32) {
        {
            size_t ga = (size_t)(m0 + ldr) * K + kc0 + ldh * 16;
            size_t gb = (size_t)(n0 + ldr) * K + kc0 + ldh * 16;
            unsigned so = ldr * RSB + ldh * 32;
            *reinterpret_cast<uint4*>(sraw + 0 * TLB + so) =
                *reinterpret_cast<const uint4*>(Ah + ga);
            *reinterpret_cast<uint4*>(sraw + 0 * TLB + so + 16) =
                *reinterpret_cast<const uint4*>(Ah + ga + 8);
            *reinterpret_cast<uint4*>(sraw + 1 * TLB + so) =
                *reinterpret_cast<const uint4*>(Am + ga);
            *reinterpret_cast<uint4*>(sraw + 1 * TLB + so + 16) =
                *reinterpret_cast<const uint4*>(Am + ga + 8);
            *reinterpret_cast<uint4*>(sraw + 2 * TLB + so) =
                *reinterpret_cast<const uint4*>(Wh + gb);
            *reinterpret_cast<uint4*>(sraw + 2 * TLB + so + 16) =
                *reinterpret_cast<const uint4*>(Wh + gb + 8);
            *reinterpret_cast<uint4*>(sraw + 3 * TLB + so) =
                *reinterpret_cast<const uint4*>(Wm + gb);
            *reinterpret_cast<uint4*>(sraw + 3 * TLB + so + 16) =
                *reinterpret_cast<const uint4*>(Wm + gb + 8);
        }
        __syncthreads();

#pragma unroll
        for (int kh = 0; kh < 2; kh++) {
#pragma unroll
            for (int ps = 0; ps < 3; ps++) {
                unsigned ab = (ps == 2) ? 1u * TLB : 0u * TLB;
                unsigned bb = (ps == 1) ? 3u * TLB : 2u * TLB;
                unsigned a[4][4], bfr[2][4];
#pragma unroll
                for (int i = 0; i < 4; i++) {
                    unsigned ao = sbase + ab +
                        (wm * 64 + i * 16 + mn_off) * RSB + (kh * 16 + k_off) * 2;
                    ldsm4(a[i][0], a[i][1], a[i][2], a[i][3], ao);
                }
#pragma unroll
                for (int j16 = 0; j16 < 2; j16++) {
                    unsigned bo = sbase + bb +
                        (wn * 32 + j16 * 16 + mn_off) * RSB + (kh * 16 + k_off) * 2;
                    ldsm4(bfr[j16][0], bfr[j16][1], bfr[j16][2], bfr[j16][3], bo);
                }
#pragma unroll
                for (int i = 0; i < 4; i++)
#pragma unroll
                    for (int j = 0; j < 4; j++) {
                        int jj = j >> 1, p = j & 1;
                        mma_bf16(d[i][j][0], d[i][j][1], d[i][j][2], d[i][j][3],
                                 a[i][0], a[i][1], a[i][2], a[i][3],
                                 bfr[jj][p], bfr[jj][p + 2]);
                    }
            }
        }
        __syncthreads();
    }

    int r = lane >> 2, c2 = (lane & 3) * 2;
#pragma unroll
    for (int i = 0; i < 4; i++) {
#pragma unroll
        for (int j = 0; j < 4; j++) {
            int colL = wn * 32 + j * 8 + c2;
            int col = n0 + colL;
            int row0 = m0 + wm * 64 + i * 16 + r;
            float2 o0, o1;
            o0.x = d[i][j][0] + sbias[colL];
            o0.y = d[i][j][1] + sbias[colL + 1];
            o1.x = d[i][j][2] + sbias[colL];
            o1.y = d[i][j][3] + sbias[colL + 1];
            *reinterpret_cast<float2*>(C + (size_t)row0 * GG + col) = o0;
            *reinterpret_cast<float2*>(C + (size_t)(row0 + 8) * GG + col) = o1;
        }
    }
}

// ---------------- persistent bidirectional LSTM recurrence (R15-exact v6) ------
#define RSH 80
#define RSW 1040
#define SWH_OFF 0u
#define SWM_OFF 33280u
#define SHH_OFF 66560u
#define SHM_OFF 107520u
#define SP_OFF  148480u
#define SG_OFF  218112u
#define REC_SMEM 222336
__global__ __launch_bounds__(512) void lstm_rec(
    const float* __restrict__ pre_f, const float* __restrict__ pre_r,
    const unsigned short* __restrict__ Whf_hi, const unsigned short* __restrict__ Whf_mi,
    const unsigned short* __restrict__ Whr_hi, const unsigned short* __restrict__ Whr_mi,
    float* __restrict__ xout) {
    extern __shared__ unsigned char smc[];
    float* sP = reinterpret_cast<float*>(smc + SP_OFF);
    float* sG = reinterpret_cast<float*>(smc + SG_OFF);
    unsigned sbase = smem_u32(smc);

    int blk = blockIdx.x;
    int dir = blk >> 6;
    int j0 = (blk & 63) * 8;
    const float* pre = dir ? pre_r : pre_f;
    const unsigned short* Whi = dir ? Whr_hi : Whf_hi;
    const unsigned short* Wmi = dir ? Whr_mi : Whf_mi;

    int tid = threadIdx.x;
    int warp = tid >> 5, lane = tid & 31;
    int rr = tid >> 4, b0 = (tid & 15) * 2;
    int r_glob = (rr >> 3) * HH + j0 + (rr & 7);
    int ua = tid >> 5, ba = tid & 31;            // activation (tid<256)
    int tl = lane >> 3, r8 = lane & 7;
    int mn_off = (tl & 1) * 8 + r8;              // B frags (n rows)
    int k_off = (tl >> 1) * 8;                   // B frags (k)
    int kA = (tl >> 1) * 8 + r8;                 // A trans frags: stored k row
    int bA = (tl & 1) * 8;                       // A trans frags: b col

    unsigned gen0 = g_gen;

    // ---- load W slice (32 rows x 512 k, hi+mid) into smem ----
    for (int i = tid; i < 2048; i += 512) {
        int row = i >> 6, c16 = i & 63;
        int g = row >> 3, u = row & 7;
        size_t src = (size_t)(g * HH + j0 + u) * 64 + c16;
        *reinterpret_cast<uint4*>(smc + SWH_OFF + row * RSW + c16 * 16) =
            reinterpret_cast<const uint4*>(Whi)[src];
        *reinterpret_cast<uint4*>(smc + SWM_OFF + row * RSW + c16 * 16) =
            reinterpret_cast<const uint4*>(Wmi)[src];
    }

    if (tid < 256) {
        g_hbh[0][dir][(j0 + ua) * BB + ba] = 0;
        g_hbm[0][dir][(j0 + ua) * BB + ba] = 0;
    }
    float creg = 0.0f;

    // ---- initial full-grid barrier (R12-exact) ----
    __threadfence();
    __syncthreads();
    if (blk == 0) {
        if (tid >= 1 && tid < 128) {
            unsigned tg = gen0 + 1u;
            while ((int)(g_arr[tid] - tg) < 0) { }
            __threadfence();
        }
        __syncthreads();
        if (tid == 0) { __threadfence(); g_gen = gen0 + 1u; }
    } else {
        if (tid == 0) {
            g_arr[blk] = gen0 + 1u;
            unsigned tg = gen0 + 1u;
            while ((int)(g_gen - tg) < 0) { }
            __threadfence();
        }
        __syncthreads();
    }

    unsigned hb = SHH_OFF + warp * 2560;
    unsigned mb = SHM_OFF + warp * 2560;
    int wk = warp * 32;

    for (int s = 0; s < TT; s++) {
        int t = dir ? (TT - 1 - s) : s;
        int cur = s & 1, nxt = cur ^ 1;

        // ---- stage this warp's 32-k chunk of split h ----
        {
            const uint4* gh = reinterpret_cast<const uint4*>(&g_hbh[cur][dir][0]) + warp * 128;
            const uint4* gm = reinterpret_cast<const uint4*>(&g_hbm[cur][dir][0]) + warp * 128;
#pragma unroll
            for (int q = 0; q < 4; q++) {
                int i = lane + 32 * q;
                unsigned so = (i >> 2) * RSH + (i & 3) * 16;
                *reinterpret_cast<uint4*>(smc + hb + so) = gh[i];
                *reinterpret_cast<uint4*>(smc + mb + so) = gm[i];
            }
        }

        const float* pre_t = pre + (size_t)t * (BB * GG) + r_glob;
        float p0 = pre_t[(size_t)(b0 + 0) * GG];
        float p1 = pre_t[(size_t)(b0 + 1) * GG];

        __syncwarp();

        // ---- HMMA dot: D[32b x 32n] partial over this warp's 32 k ----
        float d[2][4][4];
#pragma unroll
        for (int i = 0; i < 2; i++)
#pragma unroll
            for (int j = 0; j < 4; j++)
#pragma unroll
                for (int q = 0; q < 4; q++) d[i][j][q] = 0.0f;

#pragma unroll
        for (int ps = 0; ps < 3; ps++) {
            unsigned Abase = sbase + ((ps == 2) ? mb : hb);
            unsigned Bbase = sbase + ((ps == 1) ? SWM_OFF : SWH_OFF);
#pragma unroll
            for (int ks = 0; ks < 2; ks++) {
                int kb = ks * 16;
                unsigned a[2][4], bfr[2][4];
#pragma unroll
                for (int mt = 0; mt < 2; mt++) {
                    unsigned ao = Abase + (kb + kA) * RSH + (mt * 16 + bA) * 2;
                    ldsm4t(a[mt][0], a[mt][1], a[mt][2], a[mt][3], ao);
                }
#pragma unroll
                for (int j16 = 0; j16 < 2; j16++) {
                    unsigned bo = Bbase + (j16 * 16 + mn_off) * RSW +
                                  (wk + kb + k_off) * 2;
                    ldsm4(bfr[j16][0], bfr[j16][1], bfr[j16][2], bfr[j16][3], bo);
                }
#pragma unroll
                for (int mt = 0; mt < 2; mt++)
#pragma unroll
                    for (int j = 0; j < 4; j++) {
                        int jj = j >> 1, p = j & 1;
                        mma_bf16(d[mt][j][0], d[mt][j][1], d[mt][j][2], d[mt][j][3],
                                 a[mt][0], a[mt][1], a[mt][2], a[mt][3],
                                 bfr[jj][p], bfr[jj][p + 2]);
                    }
            }
        }

        // ---- write partials: sP[warp][nrow][batch] ----
        {
            int r = lane >> 2, c2 = (lane & 3) * 2;
#pragma unroll
            for (int mt = 0; mt < 2; mt++)
#pragma unroll
                for (int j = 0; j < 4; j++) {
                    int nr = j * 8 + c2;
                    int bb_ = mt * 16 + r;
                    sP[((warp * 32) + nr) * 34 + bb_]         = d[mt][j][0];
                    sP[((warp * 32) + nr + 1) * 34 + bb_]     = d[mt][j][1];
                    sP[((warp * 32) + nr) * 34 + bb_ + 8]     = d[mt][j][2];
                    sP[((warp * 32) + nr + 1) * 34 + bb_ + 8] = d[mt][j][3];
                }
        }
        __syncthreads();

        // ---- reduce 16 chunks + pre -> gates (R12-exact) ----
        {
            float s0 = p0, s1 = p1;
#pragma unroll
            for (int c = 0; c < 16; c++) {
                float2 x = *reinterpret_cast<const float2*>(
                    sP + ((c * 32) + rr) * 34 + b0);
                s0 += x.x; s1 += x.y;
            }
            float* g = sG + rr * 33 + b0;
            g[0] = s0; g[1] = s1;
        }
        __syncthreads();

        // ---- activation + split-h store (R12 pattern: per-thread fence) ----
        float h = 0.0f;
        if (tid < 256) {
            float gi = sG[(0 + ua) * 33 + ba];
            float gf = sG[(8 + ua) * 33 + ba];
            float gc = sG[(16 + ua) * 33 + ba];
            float go = sG[(24 + ua) * 33 + ba];
            creg = sigf(gf) * creg + sigf(gi) * tanhfast(gc);
            h = sigf(go) * tanhfast(creg);
            __nv_bfloat16 hh = __float2bfloat16(h);
            int ha = (j0 + ua) * BB + ba;
            g_hbh[nxt][dir][ha] = __bfloat16_as_ushort(hh);
            g_hbm[nxt][dir][ha] =
                __bfloat16_as_ushort(__float2bfloat16(h - __bfloat162float(hh)));
            __threadfence();
        }
        __syncthreads();

        // ---- full-grid barrier with xout overlap (R12-exact) ----
        unsigned tg = gen0 + (unsigned)s + 2u;
        if (blk == 0) {
            if (tid < 256)
                xout[((size_t)t * BB + ba) * H2 + dir * HH + j0 + ua] = h;
            if (tid >= 1 && tid < 128) {
                while ((int)(g_arr[tid] - tg) < 0) { }
                __threadfence();
            }
            __syncthreads();
            if (tid == 0) { __threadfence(); g_gen = tg; }
        } else {
            if (tid == 0) g_arr[blk] = tg;
            if (tid < 256)
                xout[((size_t)t * BB + ba) * H2 + dir * HH + j0 + ua] = h;
            if (tid == 0) {
                while ((int)(g_gen - tg) < 0) { }
                __threadfence();
            }
            __syncthreads();
        }
    }
}

// ---------------- classifier ----------------
__global__ void cls_k(const float* __restrict__ x2, const float* __restrict__ w,
                      const float* __restrict__ bias, float* __restrict__ out) {
    int gw = (blockIdx.x * blockDim.x + threadIdx.x) >> 5;
    int lane = threadIdx.x & 31;
    if (gw >= MM) return;
    const float* xr = x2 + (size_t)gw * H2;
    float acc[LL];
#pragma unroll
    for (int l = 0; l < LL; l++) acc[l] = 0.0f;
    for (int k = lane; k < H2; k += 32) {
        float xv = xr[k];
#pragma unroll
        for (int l = 0; l < LL; l++) acc[l] = fmaf(xv, w[l * H2 + k], acc[l]);
    }
#pragma unroll
    for (int l = 0; l < LL; l++) {
#pragma unroll
        for (int off = 16; off > 0; off >>= 1)
            acc[l] += __shfl_xor_sync(0xffffffffu, acc[l], off);
    }
    if (lane == 0) {
        int t = gw >> 5, b = gw & 31;
        float* o = out + 1 + ((size_t)b * TT + t) * LL;
#pragma unroll
        for (int l = 0; l < LL; l++) o[l] = acc[l] + bias[l];
    }
}

// ---------------- CRF NLL ----------------
__global__ void crf_k(const float* __restrict__ dout, const int* __restrict__ labels,
                      const int* __restrict__ mask, const float* __restrict__ start,
                      const float* __restrict__ endv, const float* __restrict__ trans,
                      float* __restrict__ out) {
    __shared__ float alpha[BB][LL];
    __shared__ float sc[BB];
    __shared__ float lz[BB];
    __shared__ int   prev[BB];
    __shared__ float tr[LL][LL];
    int tid = threadIdx.x;
    int b = tid / LL, l = tid % LL;
    if (tid < LL * LL) tr[tid / LL][tid % LL] = trans[tid];
    __syncthreads();
    const float* em = dout + 1;

    alpha[b][l] = start[l] + em[((size_t)b * TT) * LL + l];
    if (l == 0) {
        int tg = labels[b * TT]; if (tg < 0) tg = 0;
        sc[b] = start[tg] + em[((size_t)b * TT) * LL + tg];
        prev[b] = tg;
    }
    __syncthreads();

    for (int t = 1; t < TT; t++) {
        int on = mask[b * TT + t];
        float m = -1e30f;
#pragma unroll
        for (int p = 0; p < LL; p++) m = fmaxf(m, alpha[b][p] + tr[p][l]);
        float s = 0.0f;
#pragma unroll
        for (int p = 0; p < LL; p++) s += __expf(alpha[b][p] + tr[p][l] - m);
        float nxt = m + __logf(s) + em[((size_t)b * TT + t) * LL + l];
        __syncthreads();
        if (on) alpha[b][l] = nxt;
        if (l == 0) {
            int tg = labels[b * TT + t]; if (tg < 0) tg = 0;
            float mk = (float)mask[b * TT + t];
            sc[b] += (tr[prev[b]][tg] + em[((size_t)b * TT + t) * LL + tg]) * mk;
            if (on) prev[b] = tg;
        }
        __syncthreads();
    }
    if (l == 0) {
        sc[b] += endv[prev[b]];
        float m = -1e30f;
#pragma unroll
        for (int p = 0; p < LL; p++) m = fmaxf(m, alpha[b][p] + endv[p]);
        float s = 0.0f;
#pragma unroll
        for (int p = 0; p < LL; p++) s += __expf(alpha[b][p] + endv[p] - m);
        lz[b] = m + __logf(s);
    }
    __syncthreads();
    if (tid == 0) {
        float loss = 0.0f;
        for (int bb = 0; bb < BB; bb++) loss += sc[bb] - lz[bb];
        out[0] = -loss / (float)BB;
    }
}

// ---------------- host launch ----------------
extern "C" void kernel_launch(void* const* d_in, const int* in_sizes, int n_in,
                              void* d_out, int out_size) {
    const int*   ids    = (const int*)d_in[0];
    const int*   amask  = (const int*)d_in[1];
    const int*   labels = (const int*)d_in[2];
    const float* emb    = (const float*)d_in[3];
    const float* w_ih_l0_f = (const float*)d_in[4];
    const float* w_hh_l0_f = (const float*)d_in[5];
    const float* b_ih_l0_f = (const float*)d_in[6];
    const float* b_hh_l0_f = (const float*)d_in[7];
    const float* w_ih_l0_r = (const float*)d_in[8];
    const float* w_hh_l0_r = (const float*)d_in[9];
    const float* b_ih_l0_r = (const float*)d_in[10];
    const float* b_hh_l0_r = (const float*)d_in[11];
    const float* w_ih_l1_f = (const float*)d_in[12];
    const float* w_hh_l1_f = (const float*)d_in[13];
    const float* b_ih_l1_f = (const float*)d_in[14];
    const float* b_hh_l1_f = (const float*)d_in[15];
    const float* w_ih_l1_r = (const float*)d_in[16];
    const float* w_hh_l1_r = (const float*)d_in[17];
    const float* b_ih_l1_r = (const float*)d_in[18];
    const float* b_hh_l1_r = (const float*)d_in[19];
    const float* cls_w  = (const float*)d_in[20];
    const float* cls_b  = (const float*)d_in[21];
    const float* crf_s  = (const float*)d_in[22];
    const float* crf_e  = (const float*)d_in[23];
    const float* crf_t  = (const float*)d_in[24];
    float* out = (float*)d_out;

    float *x1, *x2, *pref, *prer;
    unsigned short *ah, *am, *whh_h, *whh_m;
    cudaGetSymbolAddress((void**)&x1,    g_x1);
    cudaGetSymbolAddress((void**)&x2,    g_x2);
    cudaGetSymbolAddress((void**)&pref,  g_pre_f);
    cudaGetSymbolAddress((void**)&prer,  g_pre_r);
    cudaGetSymbolAddress((void**)&ah,    g_Ah);
    cudaGetSymbolAddress((void**)&am,    g_Am);
    cudaGetSymbolAddress((void**)&whh_h, g_WHh);
    cudaGetSymbolAddress((void**)&whh_m, g_WHm);

    cudaFuncSetAttribute(lstm_rec, cudaFuncAttributeMaxDynamicSharedMemorySize, REC_SMEM);

    embed_split<<<(MM * EE / 4 + 255) / 256, 256>>>(ids, emb, ah, am);
    {
        dim3 g4((NW / 4 + 255) / 256, 4);
        split4_whh<<<g4, 256>>>(w_hh_l0_f, w_hh_l0_r, w_hh_l1_f, w_hh_l1_r,
                                whh_h, whh_m);
    }
    {
        dim3 g2((GG * EE / 4 + 255) / 256, 2);
        split2_wih<<<g2, 256>>>(w_ih_l0_f, w_ih_l0_r, GG * EE / 4);
    }
    {
        dim3 gg(GG / 128, MM / 128, 2);
        gemm_mma<<<gg, 256>>>(ah, am, EE,
                              b_ih_l0_f, b_hh_l0_f, b_ih_l0_r, b_hh_l0_r,
                              pref, prer);
    }
    lstm_rec<<<128, 512, REC_SMEM>>>(pref, prer,
                                     whh_h + 0 * NW, whh_m + 0 * NW,
                                     whh_h + 1 * NW, whh_m + 1 * NW, x1);

    split_bf16<<<(MM * H2 / 4 + 255) / 256, 256>>>(x1, ah, am, MM * H2 / 4);
    {
        dim3 g2((GG * H2 / 4 + 255) / 256, 2);
        split2_wih<<<g2, 256>>>(w_ih_l1_f, w_ih_l1_r, GG * H2 / 4);
    }
    {
        dim3 gg(GG / 128, MM / 128, 2);
        gemm_mma<<<gg, 256>>>(ah, am, H2,
                              b_ih_l1_f, b_hh_l1_f, b_ih_l1_r, b_hh_l1_r,
                              pref, prer);
    }
    lstm_rec<<<128, 512, REC_SMEM>>>(pref, prer,
                                     whh_h + 2 * NW, whh_m + 2 * NW,
                                     whh_h + 3 * NW, whh_m + 3 * NW, x2);

    cls_k<<<(MM * 32 + 255) / 256, 256>>>(x2, cls_w, cls_b, out);
    crf_k<<<1, BB * LL>>>(out, labels, amask, crf_s, crf_e, crf_t, out);
}